// round 1
// baseline (speedup 1.0000x reference)
#include <cuda_runtime.h>
#include <math.h>

#define N_SEG 12800
#define D_ 128
#define S_ 100
#define B_ 16
#define M_ 8
#define P_ 40
#define OUT_ELEMS (S_*B_*M_*D_)   // 1638400
#define FULLMASK 0xffffffffu

// ---------------- precomputed folded weights ----------------
__device__ float g_score_w[24];     // [a*8+h]  (includes HD^-0.5 scale)
__device__ float g_score_c[8];
__device__ float g_W2[24*128];      // [(h*3+a)*128 + j]
__device__ float g_c2[128];
__device__ float g_emb[N_SEG*D_];   // post-LN1 embeddings (scratch, 6.5MB)

// ================= kernel 1: fold weights =================
__global__ void k_pre(const float* __restrict__ ms,   const float* __restrict__ lin_w,
                      const float* __restrict__ lin_b,const float* __restrict__ wq,
                      const float* __restrict__ wk,   const float* __restrict__ wv,
                      const float* __restrict__ bq,   const float* __restrict__ bk,
                      const float* __restrict__ bv,   const float* __restrict__ out_w,
                      const float* __restrict__ out_b)
{
    __shared__ float q[128];
    __shared__ float wkq[128*8];
    __shared__ float lwv[3*128];
    __shared__ float cv[128];
    const int t = threadIdx.x;   // 128 threads

    // q = map_seeds @ wq + bq
    {
        float acc = bq[t];
        for (int e = 0; e < 128; e++) acc += ms[e]*wq[e*128+t];
        q[t] = acc;
    }
    __syncthreads();

    // wkq[d][h] = sum_j wk[d, 16h+j] * q[16h+j]
    #pragma unroll
    for (int h = 0; h < 8; h++) {
        float s = 0.f;
        #pragma unroll
        for (int j = 0; j < 16; j++) s += wk[t*128 + h*16 + j]*q[h*16 + j];
        wkq[t*8 + h] = s;
    }
    __syncthreads();

    if (t < 24) {
        int a = t/8, h = t%8;
        float s = 0.f;
        for (int d = 0; d < 128; d++) s += lin_w[a*128+d]*wkq[d*8+h];
        g_score_w[a*8+h] = 0.25f*s;
    } else if (t < 32) {
        int h = t-24;
        float s = 0.f;
        for (int d = 0; d < 128; d++) s += lin_b[d]*wkq[d*8+h];
        for (int j = 0; j < 16; j++) s += q[h*16+j]*bk[h*16+j];
        g_score_c[h] = 0.25f*s;
    }

    // lwv[a][d] = (lin_w @ wv)[a,d] ; cv[d] = lin_b @ wv + bv
    {
        float s0=0.f, s1=0.f, s2=0.f, sc=0.f;
        for (int e = 0; e < 128; e++) {
            float w = wv[e*128 + t];
            s0 += lin_w[0*128+e]*w;
            s1 += lin_w[1*128+e]*w;
            s2 += lin_w[2*128+e]*w;
            sc += lin_b[e]*w;
        }
        lwv[0*128+t]=s0; lwv[1*128+t]=s1; lwv[2*128+t]=s2;
        cv[t] = sc + bv[t];
    }
    __syncthreads();

    // W2[(h*3+a)][j] = sum_{d in head h} lwv[a][d]*out_w[d][j]
    #pragma unroll
    for (int h = 0; h < 8; h++) {
        #pragma unroll
        for (int a = 0; a < 3; a++) {
            float s = 0.f;
            #pragma unroll
            for (int dd = 0; dd < 16; dd++) {
                int d = h*16 + dd;
                s += lwv[a*128+d]*out_w[d*128+t];
            }
            g_W2[(h*3+a)*128 + t] = s;
        }
    }
    // c2[j] = cv @ out_w + out_b
    {
        float s = out_b[t];
        for (int d = 0; d < 128; d++) s += cv[d]*out_w[d*128+t];
        g_c2[t] = s;
    }
}

// ================= kernel 2: attention pooling + LN1 =================
// one warp per segment
__global__ void k_attn(const float* __restrict__ roads,
                       const float* __restrict__ ln1_g, const float* __restrict__ ln1_b,
                       float* __restrict__ d_out)
{
    const int n    = (blockIdx.x*blockDim.x + threadIdx.x) >> 5;
    const int lane = threadIdx.x & 31;
    if (n >= N_SEG) return;

    const float4* rp = reinterpret_cast<const float4*>(roads) + n*P_;
    float4 a0 = rp[lane];
    float4 a1 = make_float4(0.f,0.f,0.f,0.f);
    if (lane < 8) a1 = rp[32 + lane];

    bool v0 = (a0.w != 0.0f);
    bool v1 = (lane < 8) && (a1.w != 0.0f);
    unsigned bm0 = __ballot_sync(FULLMASK, v0);
    unsigned bm1 = __ballot_sync(FULLMASK, v1);
    const bool seg_empty = ((bm0 | bm1) == 0u);
    if (seg_empty && lane == 0) v0 = true;   // unmask pt0 of empty segment

    float pa[24];
    #pragma unroll
    for (int h = 0; h < 8; h++) {
        const float sw0 = __ldg(&g_score_w[0*8+h]);
        const float sw1 = __ldg(&g_score_w[1*8+h]);
        const float sw2 = __ldg(&g_score_w[2*8+h]);
        const float sc  = __ldg(&g_score_c[h]);
        float s0 = sc + a0.x*sw0 + a0.y*sw1 + a0.z*sw2;
        float s1 = sc + a1.x*sw0 + a1.y*sw1 + a1.z*sw2;
        float mx = fmaxf(v0 ? s0 : -1e30f, v1 ? s1 : -1e30f);
        #pragma unroll
        for (int o = 16; o; o >>= 1) mx = fmaxf(mx, __shfl_xor_sync(FULLMASK, mx, o));
        float e0 = v0 ? __expf(s0 - mx) : 0.0f;
        float e1 = v1 ? __expf(s1 - mx) : 0.0f;
        float t0 = e0 + e1;
        float t1 = e0*a0.x + e1*a1.x;
        float t2 = e0*a0.y + e1*a1.y;
        float t3 = e0*a0.z + e1*a1.z;
        #pragma unroll
        for (int o = 16; o; o >>= 1) {
            t0 += __shfl_xor_sync(FULLMASK, t0, o);
            t1 += __shfl_xor_sync(FULLMASK, t1, o);
            t2 += __shfl_xor_sync(FULLMASK, t2, o);
            t3 += __shfl_xor_sync(FULLMASK, t3, o);
        }
        float inv = 1.0f / t0;
        pa[h*3+0] = t1*inv;
        pa[h*3+1] = t2*inv;
        pa[h*3+2] = t3*inv;
    }

    // y = pa(24) @ W2(24x128) + c2 ; lane owns cols lane+32u
    float y[4];
    #pragma unroll
    for (int u = 0; u < 4; u++) {
        int j = lane + 32*u;
        float acc = __ldg(&g_c2[j]);
        #pragma unroll
        for (int i = 0; i < 24; i++) acc += pa[i]*__ldg(&g_W2[i*128 + j]);
        y[u] = acc;
    }

    // LayerNorm 1
    float loc = y[0]+y[1]+y[2]+y[3];
    #pragma unroll
    for (int o = 16; o; o >>= 1) loc += __shfl_xor_sync(FULLMASK, loc, o);
    const float mu = loc * (1.0f/128.0f);
    float sq = 0.f;
    #pragma unroll
    for (int u = 0; u < 4; u++) { float d = y[u]-mu; sq += d*d; }
    #pragma unroll
    for (int o = 16; o; o >>= 1) sq += __shfl_xor_sync(FULLMASK, sq, o);
    const float istd = rsqrtf(sq*(1.0f/128.0f) + 1e-5f);
    #pragma unroll
    for (int u = 0; u < 4; u++) {
        int j = lane + 32*u;
        g_emb[n*128 + j] = (y[u]-mu)*istd*__ldg(&ln1_g[j]) + __ldg(&ln1_b[j]);
    }

    if (lane == 0) d_out[OUT_ELEMS + n] = seg_empty ? 1.0f : 0.0f;
}

// ================= kernel 3: FFN + residual + LN2 + transpose =================
// 64 rows per block, 256 threads. smem: emb(64x128) + wtile(32x384) + H(64x384)
#define TILE_M 64
#define K3_SMEM_BYTES ((64*128 + 32*384 + 64*384)*4)

__global__ __launch_bounds__(256, 1)
void k_ffn(const float* __restrict__ w1, const float* __restrict__ b1,
           const float* __restrict__ w2, const float* __restrict__ b2,
           const float* __restrict__ ln2_g, const float* __restrict__ ln2_b,
           float* __restrict__ d_out)
{
    extern __shared__ float sm[];
    float* s_emb = sm;                    // 64*128
    float* s_w   = sm + 64*128;           // 32*384 (reused as 32*128 in phase 2)
    float* s_h   = s_w + 32*384;          // 64*384

    const int tid  = threadIdx.x;
    const int ty   = tid >> 5;            // 0..7 -> rows ty*8..ty*8+7
    const int tx   = tid & 31;
    const int base = blockIdx.x * TILE_M;

    for (int i = tid; i < TILE_M*128; i += 256) s_emb[i] = g_emb[base*128 + i];
    __syncthreads();

    // ---- phase 1: H = relu(emb @ w1 + b1),  w1: 128x384 ----
    float acc[8][12];
    #pragma unroll
    for (int i = 0; i < 8; i++)
        #pragma unroll
        for (int j = 0; j < 12; j++) acc[i][j] = 0.f;

    for (int kt = 0; kt < 4; kt++) {
        for (int i = tid; i < 32*384; i += 256) s_w[i] = w1[kt*32*384 + i];
        __syncthreads();
        #pragma unroll 4
        for (int kk = 0; kk < 32; kk++) {
            float a[8];
            #pragma unroll
            for (int i = 0; i < 8; i++) a[i] = s_emb[(ty*8+i)*128 + kt*32 + kk];
            const float4* bp = reinterpret_cast<const float4*>(&s_w[kk*384 + tx*12]);
            float4 q0 = bp[0], q1 = bp[1], q2 = bp[2];
            float bb[12] = {q0.x,q0.y,q0.z,q0.w, q1.x,q1.y,q1.z,q1.w, q2.x,q2.y,q2.z,q2.w};
            #pragma unroll
            for (int i = 0; i < 8; i++)
                #pragma unroll
                for (int j = 0; j < 12; j++) acc[i][j] += a[i]*bb[j];
        }
        __syncthreads();
    }
    #pragma unroll
    for (int i = 0; i < 8; i++)
        #pragma unroll
        for (int j = 0; j < 12; j++) {
            float v = acc[i][j] + __ldg(&b1[tx*12 + j]);
            s_h[(ty*8+i)*384 + tx*12 + j] = fmaxf(v, 0.0f);
        }
    __syncthreads();

    // ---- phase 2: Y = H @ w2 + b2,  w2: 384x128 ----
    float acc2[8][4];
    #pragma unroll
    for (int i = 0; i < 8; i++)
        #pragma unroll
        for (int j = 0; j < 4; j++) acc2[i][j] = 0.f;

    for (int kt = 0; kt < 12; kt++) {
        for (int i = tid; i < 32*128; i += 256) s_w[i] = w2[kt*32*128 + i];
        __syncthreads();
        #pragma unroll 4
        for (int kk = 0; kk < 32; kk++) {
            float a[8];
            #pragma unroll
            for (int i = 0; i < 8; i++) a[i] = s_h[(ty*8+i)*384 + kt*32 + kk];
            float4 b4 = *reinterpret_cast<const float4*>(&s_w[kk*128 + tx*4]);
            #pragma unroll
            for (int i = 0; i < 8; i++) {
                acc2[i][0] += a[i]*b4.x;
                acc2[i][1] += a[i]*b4.y;
                acc2[i][2] += a[i]*b4.z;
                acc2[i][3] += a[i]*b4.w;
            }
        }
        __syncthreads();
    }

    // ---- epilogue: residual + LN2 + transposed scatter ----
    const float4 bb2 = *reinterpret_cast<const float4*>(&b2[tx*4]);
    const float4 lg  = *reinterpret_cast<const float4*>(&ln2_g[tx*4]);
    const float4 lb  = *reinterpret_cast<const float4*>(&ln2_b[tx*4]);
    #pragma unroll
    for (int i = 0; i < 8; i++) {
        const int r = ty*8 + i;
        const int n = base + r;
        float v[4];
        v[0] = acc2[i][0] + bb2.x + s_emb[r*128 + tx*4 + 0];
        v[1] = acc2[i][1] + bb2.y + s_emb[r*128 + tx*4 + 1];
        v[2] = acc2[i][2] + bb2.z + s_emb[r*128 + tx*4 + 2];
        v[3] = acc2[i][3] + bb2.w + s_emb[r*128 + tx*4 + 3];
        float loc = v[0]+v[1]+v[2]+v[3];
        #pragma unroll
        for (int o = 16; o; o >>= 1) loc += __shfl_xor_sync(FULLMASK, loc, o);
        const float mu = loc * (1.0f/128.0f);
        float sq = 0.f;
        #pragma unroll
        for (int j = 0; j < 4; j++) { float d = v[j]-mu; sq += d*d; }
        #pragma unroll
        for (int o = 16; o; o >>= 1) sq += __shfl_xor_sync(FULLMASK, sq, o);
        const float istd = rsqrtf(sq*(1.0f/128.0f) + 1e-5f);

        const int s = n % S_;
        const int bm = n / S_;
        const int b = bm >> 3;
        const int m = bm & 7;
        float4 o4;
        o4.x = (v[0]-mu)*istd*lg.x + lb.x;
        o4.y = (v[1]-mu)*istd*lg.y + lb.y;
        o4.z = (v[2]-mu)*istd*lg.z + lb.z;
        o4.w = (v[3]-mu)*istd*lg.w + lb.w;
        *reinterpret_cast<float4*>(&d_out[((s*B_ + b)*M_ + m)*D_ + tx*4]) = o4;
    }
}

// ================= kernel 4: seg_mask all_seg fix =================
__global__ void k_maskfix(float* __restrict__ d_out)
{
    const int t = threadIdx.x;   // 128 = B*M
    float allm = 1.0f;
    for (int s = 0; s < S_; s++) allm = fminf(allm, d_out[OUT_ELEMS + t*S_ + s]);
    if (allm > 0.5f) d_out[OUT_ELEMS + t*S_] = 0.0f;
}

// ================= launcher =================
extern "C" void kernel_launch(void* const* d_in, const int* in_sizes, int n_in,
                              void* d_out, int out_size)
{
    const float* roads  = (const float*)d_in[0];
    // d_in[1] = agents_emb (unused by the reference output)
    const float* ms     = (const float*)d_in[2];
    const float* lin_w  = (const float*)d_in[3];
    const float* lin_b  = (const float*)d_in[4];
    const float* wq     = (const float*)d_in[5];
    const float* wk     = (const float*)d_in[6];
    const float* wv     = (const float*)d_in[7];
    const float* bq     = (const float*)d_in[8];
    const float* bk     = (const float*)d_in[9];
    const float* bv     = (const float*)d_in[10];
    const float* out_w  = (const float*)d_in[11];
    const float* out_b  = (const float*)d_in[12];
    const float* ln1_g  = (const float*)d_in[13];
    const float* ln1_b  = (const float*)d_in[14];
    const float* w1     = (const float*)d_in[15];
    const float* b1     = (const float*)d_in[16];
    const float* w2     = (const float*)d_in[17];
    const float* b2     = (const float*)d_in[18];
    const float* ln2_g  = (const float*)d_in[19];
    const float* ln2_b  = (const float*)d_in[20];
    float* out = (float*)d_out;

    cudaFuncSetAttribute(k_ffn, cudaFuncAttributeMaxDynamicSharedMemorySize, K3_SMEM_BYTES);

    k_pre<<<1, 128>>>(ms, lin_w, lin_b, wq, wk, wv, bq, bk, bv, out_w, out_b);
    k_attn<<<N_SEG/8, 256>>>(roads, ln1_g, ln1_b, out);
    k_maskfix<<<1, 128>>>(out);
    k_ffn<<<N_SEG/TILE_M, 256, K3_SMEM_BYTES>>>(w1, b1, w2, b2, ln2_g, ln2_b, out);
}

// round 3
// speedup vs baseline: 1.5367x; 1.5367x over previous
#include <cuda_runtime.h>
#include <cuda_bf16.h>
#include <math.h>
#include <stdint.h>

#define N_SEG 12800
#define D_ 128
#define S_ 100
#define B_ 16
#define M_ 8
#define P_ 40
#define OUT_ELEMS (S_*B_*M_*D_)   // 1638400
#define FULLMASK 0xffffffffu

// padded row stride for all smem/global bf16 tiles (bank-conflict-free frags)
#define LDT 136
#define TILE_E (128*LDT)          // elems per 128x128 padded tile (17408)

// ---------------- precomputed folded weights ----------------
__device__ float g_score_w[24];     // [a*8+h]
__device__ float g_score_c[8];
__device__ float g_W2[24*128];      // [(h*3+a)*128 + j]
__device__ float g_c2[128];
__device__ float g_emb[N_SEG*D_];   // post-LN1 embeddings (6.5MB scratch)

// pre-split bf16 weight tiles, padded [n][LDT]:
// tiles 0..2 = w1 n-chunks (Bt[n][k] = w1[k][nc*128+n]), 3..5 = w2 k-chunks
__device__ __align__(16) __nv_bfloat16 g_wb[6*2*TILE_E];

__device__ __forceinline__ unsigned pk2(float a, float b) {
    __nv_bfloat162 t = __floats2bfloat162_rn(a, b);
    return *reinterpret_cast<unsigned*>(&t);
}
__device__ __forceinline__ float blo(float x) {
    return x - __bfloat162float(__float2bfloat16(x));
}
__device__ __forceinline__ void mma16816(float* c, const uint32_t* a, uint32_t b0, uint32_t b1) {
    asm volatile("mma.sync.aligned.m16n8k16.row.col.f32.bf16.bf16.f32 "
        "{%0,%1,%2,%3}, {%4,%5,%6,%7}, {%8,%9}, {%0,%1,%2,%3};"
        : "+f"(c[0]), "+f"(c[1]), "+f"(c[2]), "+f"(c[3])
        : "r"(a[0]), "r"(a[1]), "r"(a[2]), "r"(a[3]), "r"(b0), "r"(b1));
}

// ================= kernel 1: fold weights =================
__global__ void k_pre(const float* __restrict__ ms,   const float* __restrict__ lin_w,
                      const float* __restrict__ lin_b,const float* __restrict__ wq,
                      const float* __restrict__ wk,   const float* __restrict__ wv,
                      const float* __restrict__ bq,   const float* __restrict__ bk,
                      const float* __restrict__ bv,   const float* __restrict__ out_w,
                      const float* __restrict__ out_b)
{
    __shared__ float q[128];
    __shared__ float wkq[128*8];
    __shared__ float lwv[3*128];
    __shared__ float cv[128];
    const int t = threadIdx.x;   // 128 threads

    {
        float acc = bq[t];
        for (int e = 0; e < 128; e++) acc += ms[e]*wq[e*128+t];
        q[t] = acc;
    }
    __syncthreads();

    #pragma unroll
    for (int h = 0; h < 8; h++) {
        float s = 0.f;
        #pragma unroll
        for (int j = 0; j < 16; j++) s += wk[t*128 + h*16 + j]*q[h*16 + j];
        wkq[t*8 + h] = s;
    }
    __syncthreads();

    if (t < 24) {
        int a = t/8, h = t%8;
        float s = 0.f;
        for (int d = 0; d < 128; d++) s += lin_w[a*128+d]*wkq[d*8+h];
        g_score_w[a*8+h] = 0.25f*s;
    } else if (t < 32) {
        int h = t-24;
        float s = 0.f;
        for (int d = 0; d < 128; d++) s += lin_b[d]*wkq[d*8+h];
        for (int j = 0; j < 16; j++) s += q[h*16+j]*bk[h*16+j];
        g_score_c[h] = 0.25f*s;
    }

    {
        float s0=0.f, s1=0.f, s2=0.f, sc=0.f;
        for (int e = 0; e < 128; e++) {
            float w = wv[e*128 + t];
            s0 += lin_w[0*128+e]*w;
            s1 += lin_w[1*128+e]*w;
            s2 += lin_w[2*128+e]*w;
            sc += lin_b[e]*w;
        }
        lwv[0*128+t]=s0; lwv[1*128+t]=s1; lwv[2*128+t]=s2;
        cv[t] = sc + bv[t];
    }
    __syncthreads();

    #pragma unroll
    for (int h = 0; h < 8; h++)
        #pragma unroll
        for (int a = 0; a < 3; a++) {
            float s = 0.f;
            #pragma unroll
            for (int dd = 0; dd < 16; dd++) {
                int d = h*16 + dd;
                s += lwv[a*128+d]*out_w[d*128+t];
            }
            g_W2[(h*3+a)*128 + t] = s;
        }
    {
        float s = out_b[t];
        for (int d = 0; d < 128; d++) s += cv[d]*out_w[d*128+t];
        g_c2[t] = s;
    }
}

// ================= kernel 1b: split FFN weights to padded bf16 hi/lo =================
__global__ void k_prew(const float* __restrict__ w1, const float* __restrict__ w2)
{
    const int w = blockIdx.x;
    __nv_bfloat16* dh = g_wb + (w*2+0)*TILE_E;
    __nv_bfloat16* dl = g_wb + (w*2+1)*TILE_E;
    for (int i = threadIdx.x; i < 128*128; i += 256) {
        int n = i >> 7, k = i & 127;
        float v = (w < 3) ? w1[k*384 + w*128 + n]
                          : w2[((w-3)*128 + k)*128 + n];
        __nv_bfloat16 h = __float2bfloat16(v);
        dh[n*LDT + k] = h;
        dl[n*LDT + k] = __float2bfloat16(v - __bfloat162float(h));
    }
}

// ================= kernel 2: attention pooling + LN1 =================
__global__ void k_attn(const float* __restrict__ roads,
                       const float* __restrict__ ln1_g, const float* __restrict__ ln1_b,
                       float* __restrict__ d_out)
{
    const int n    = (blockIdx.x*blockDim.x + threadIdx.x) >> 5;
    const int lane = threadIdx.x & 31;
    if (n >= N_SEG) return;

    const float4* rp = reinterpret_cast<const float4*>(roads) + n*P_;
    float4 a0 = rp[lane];
    float4 a1 = make_float4(0.f,0.f,0.f,0.f);
    if (lane < 8) a1 = rp[32 + lane];

    bool v0 = (a0.w != 0.0f);
    bool v1 = (lane < 8) && (a1.w != 0.0f);
    unsigned bm0 = __ballot_sync(FULLMASK, v0);
    unsigned bm1 = __ballot_sync(FULLMASK, v1);
    const bool seg_empty = ((bm0 | bm1) == 0u);
    if (seg_empty && lane == 0) v0 = true;

    float pa[24];
    #pragma unroll
    for (int h = 0; h < 8; h++) {
        const float sw0 = __ldg(&g_score_w[0*8+h]);
        const float sw1 = __ldg(&g_score_w[1*8+h]);
        const float sw2 = __ldg(&g_score_w[2*8+h]);
        const float sc  = __ldg(&g_score_c[h]);
        float s0 = sc + a0.x*sw0 + a0.y*sw1 + a0.z*sw2;
        float s1 = sc + a1.x*sw0 + a1.y*sw1 + a1.z*sw2;
        float mx = fmaxf(v0 ? s0 : -1e30f, v1 ? s1 : -1e30f);
        #pragma unroll
        for (int o = 16; o; o >>= 1) mx = fmaxf(mx, __shfl_xor_sync(FULLMASK, mx, o));
        float e0 = v0 ? __expf(s0 - mx) : 0.0f;
        float e1 = v1 ? __expf(s1 - mx) : 0.0f;
        float t0 = e0 + e1;
        float t1 = e0*a0.x + e1*a1.x;
        float t2 = e0*a0.y + e1*a1.y;
        float t3 = e0*a0.z + e1*a1.z;
        #pragma unroll
        for (int o = 16; o; o >>= 1) {
            t0 += __shfl_xor_sync(FULLMASK, t0, o);
            t1 += __shfl_xor_sync(FULLMASK, t1, o);
            t2 += __shfl_xor_sync(FULLMASK, t2, o);
            t3 += __shfl_xor_sync(FULLMASK, t3, o);
        }
        float inv = 1.0f / t0;
        pa[h*3+0] = t1*inv;
        pa[h*3+1] = t2*inv;
        pa[h*3+2] = t3*inv;
    }

    float y[4];
    #pragma unroll
    for (int u = 0; u < 4; u++) {
        int j = lane + 32*u;
        float acc = __ldg(&g_c2[j]);
        #pragma unroll
        for (int i = 0; i < 24; i++) acc += pa[i]*__ldg(&g_W2[i*128 + j]);
        y[u] = acc;
    }

    float loc = y[0]+y[1]+y[2]+y[3];
    #pragma unroll
    for (int o = 16; o; o >>= 1) loc += __shfl_xor_sync(FULLMASK, loc, o);
    const float mu = loc * (1.0f/128.0f);
    float sq = 0.f;
    #pragma unroll
    for (int u = 0; u < 4; u++) { float d = y[u]-mu; sq += d*d; }
    #pragma unroll
    for (int o = 16; o; o >>= 1) sq += __shfl_xor_sync(FULLMASK, sq, o);
    const float istd = rsqrtf(sq*(1.0f/128.0f) + 1e-5f);
    #pragma unroll
    for (int u = 0; u < 4; u++) {
        int j = lane + 32*u;
        g_emb[n*128 + j] = (y[u]-mu)*istd*__ldg(&ln1_g[j]) + __ldg(&ln1_b[j]);
    }

    if (lane == 0) d_out[OUT_ELEMS + n] = seg_empty ? 1.0f : 0.0f;
}

// ================= kernel 3: HMMA split-bf16 FFN + residual + LN2 =================
// grid=100, block=256 (8 warps: 4 m-groups x 2 n-groups, each warp m32 x n64)
// smem tiles (bf16, padded LDT=136): AH AL HH HL BH BL = 6 x 34816B = 208896B
#define T_BYTES (TILE_E*2)          // 34816
#define K3_DSMEM (6*T_BYTES)

// one gemm pass: acc[2][8][4] += A[mbase..+32][0..127] * Bt[nbase..+64][0..127]^T
__device__ __forceinline__ void gemm_pass(const __nv_bfloat16* __restrict__ sA,
                                          const __nv_bfloat16* __restrict__ sB,
                                          int mbase, int nbase, int qr, int qc,
                                          float (&acc)[2][8][4])
{
    #pragma unroll
    for (int k = 0; k < 8; k++) {
        uint32_t a[2][4];
        #pragma unroll
        for (int mt = 0; mt < 2; mt++) {
            const __nv_bfloat16* ap = sA + (mbase + mt*16 + qr)*LDT + k*16 + qc;
            a[mt][0] = *reinterpret_cast<const uint32_t*>(ap);
            a[mt][1] = *reinterpret_cast<const uint32_t*>(ap + 8*LDT);
            a[mt][2] = *reinterpret_cast<const uint32_t*>(ap + 8);
            a[mt][3] = *reinterpret_cast<const uint32_t*>(ap + 8*LDT + 8);
        }
        #pragma unroll
        for (int nt = 0; nt < 8; nt++) {
            const __nv_bfloat16* bp = sB + (nbase + nt*8 + qr)*LDT + k*16 + qc;
            uint32_t b0 = *reinterpret_cast<const uint32_t*>(bp);
            uint32_t b1 = *reinterpret_cast<const uint32_t*>(bp + 8);
            mma16816(acc[0][nt], a[0], b0, b1);
            mma16816(acc[1][nt], a[1], b0, b1);
        }
    }
}

__global__ __launch_bounds__(256, 1)
void k_ffn_mma(const float* __restrict__ b1, const float* __restrict__ b2,
               const float* __restrict__ ln2_g, const float* __restrict__ ln2_b,
               float* __restrict__ d_out)
{
    extern __shared__ __align__(16) char smem[];
    __nv_bfloat16* sAh = reinterpret_cast<__nv_bfloat16*>(smem);
    __nv_bfloat16* sAl = sAh + TILE_E;
    __nv_bfloat16* sHh = sAl + TILE_E;
    __nv_bfloat16* sHl = sHh + TILE_E;
    __nv_bfloat16* sBh = sHl + TILE_E;
    __nv_bfloat16* sBl = sBh + TILE_E;

    const int tid  = threadIdx.x;
    const int wid  = tid >> 5;
    const int lane = tid & 31;
    const int qr   = lane >> 2;          // 0..7
    const int qc   = (lane & 3) << 1;    // 0,2,4,6
    const int mbase = (wid >> 1) * 32;
    const int nbase = (wid & 1) * 64;
    const int base  = blockIdx.x * 128;

    // ---- stage A = emb tile (bf16 hi/lo) ----
    {
        const float4* eb = reinterpret_cast<const float4*>(g_emb + base*128);
        for (int i = tid; i < 4096; i += 256) {
            int r = i >> 5, c4 = (i & 31) << 2;
            float4 v = eb[i];
            int off = r*LDT + c4;
            *reinterpret_cast<uint2*>(sAh + off) = make_uint2(pk2(v.x,v.y), pk2(v.z,v.w));
            *reinterpret_cast<uint2*>(sAl + off) =
                make_uint2(pk2(blo(v.x),blo(v.y)), pk2(blo(v.z),blo(v.w)));
        }
    }

    float acc2[2][8][4];
    #pragma unroll
    for (int mt = 0; mt < 2; mt++)
        #pragma unroll
        for (int nt = 0; nt < 8; nt++)
            #pragma unroll
            for (int c = 0; c < 4; c++) acc2[mt][nt][c] = 0.f;

    for (int kc = 0; kc < 3; kc++) {
        // ---- stage W1 chunk ----
        __syncthreads();
        {
            const float4* sh = reinterpret_cast<const float4*>(g_wb + (kc*2+0)*TILE_E);
            const float4* sl = reinterpret_cast<const float4*>(g_wb + (kc*2+1)*TILE_E);
            for (int i = tid; i < T_BYTES/16; i += 256) {
                reinterpret_cast<float4*>(sBh)[i] = sh[i];
                reinterpret_cast<float4*>(sBl)[i] = sl[i];
            }
        }
        __syncthreads();

        // ---- layer1: acc1 = A @ W1c (3 passes) ----
        float acc1[2][8][4];
        #pragma unroll
        for (int mt = 0; mt < 2; mt++)
            #pragma unroll
            for (int nt = 0; nt < 8; nt++)
                #pragma unroll
                for (int c = 0; c < 4; c++) acc1[mt][nt][c] = 0.f;
        gemm_pass(sAh, sBh, mbase, nbase, qr, qc, acc1);
        gemm_pass(sAh, sBl, mbase, nbase, qr, qc, acc1);
        gemm_pass(sAl, sBh, mbase, nbase, qr, qc, acc1);

        // ---- relu + bias + split -> sH ----
        #pragma unroll
        for (int mt = 0; mt < 2; mt++)
            #pragma unroll
            for (int nt = 0; nt < 8; nt++) {
                const int row = mbase + mt*16 + qr;
                const int col = nbase + nt*8 + qc;
                const int cg  = kc*128 + col;
                float v0 = fmaxf(acc1[mt][nt][0] + __ldg(&b1[cg]),   0.f);
                float v1 = fmaxf(acc1[mt][nt][1] + __ldg(&b1[cg+1]), 0.f);
                float v2 = fmaxf(acc1[mt][nt][2] + __ldg(&b1[cg]),   0.f);
                float v3 = fmaxf(acc1[mt][nt][3] + __ldg(&b1[cg+1]), 0.f);
                *reinterpret_cast<uint32_t*>(sHh + row*LDT + col)     = pk2(v0, v1);
                *reinterpret_cast<uint32_t*>(sHl + row*LDT + col)     = pk2(blo(v0), blo(v1));
                *reinterpret_cast<uint32_t*>(sHh + (row+8)*LDT + col) = pk2(v2, v3);
                *reinterpret_cast<uint32_t*>(sHl + (row+8)*LDT + col) = pk2(blo(v2), blo(v3));
            }
        __syncthreads();

        // ---- stage W2 chunk ----
        {
            const float4* sh = reinterpret_cast<const float4*>(g_wb + ((3+kc)*2+0)*TILE_E);
            const float4* sl = reinterpret_cast<const float4*>(g_wb + ((3+kc)*2+1)*TILE_E);
            for (int i = tid; i < T_BYTES/16; i += 256) {
                reinterpret_cast<float4*>(sBh)[i] = sh[i];
                reinterpret_cast<float4*>(sBl)[i] = sl[i];
            }
        }
        __syncthreads();

        // ---- layer2 partial: acc2 += Hc @ W2c (3 passes) ----
        gemm_pass(sHh, sBh, mbase, nbase, qr, qc, acc2);
        gemm_pass(sHh, sBl, mbase, nbase, qr, qc, acc2);
        gemm_pass(sHl, sBh, mbase, nbase, qr, qc, acc2);
    }
    __syncthreads();

    // ---- dump acc2 + bias + residual to f32 smem buffer [128][132] ----
    float* sF = reinterpret_cast<float*>(smem);
    #pragma unroll
    for (int mt = 0; mt < 2; mt++)
        #pragma unroll
        for (int nt = 0; nt < 8; nt++) {
            const int row = mbase + mt*16 + qr;
            const int col = nbase + nt*8 + qc;
            const float2 e0 = *reinterpret_cast<const float2*>(&g_emb[(base+row)*128 + col]);
            const float2 e1 = *reinterpret_cast<const float2*>(&g_emb[(base+row+8)*128 + col]);
            const float bb0 = __ldg(&b2[col]), bb1 = __ldg(&b2[col+1]);
            sF[row*132 + col]       = acc2[mt][nt][0] + bb0 + e0.x;
            sF[row*132 + col + 1]   = acc2[mt][nt][1] + bb1 + e0.y;
            sF[(row+8)*132 + col]   = acc2[mt][nt][2] + bb0 + e1.x;
            sF[(row+8)*132 + col+1] = acc2[mt][nt][3] + bb1 + e1.y;
        }
    __syncthreads();

    // ---- LN2 + transposed store ----
    if (tid < 128) {
        const int row = tid;
        float sum = 0.f, sq = 0.f;
        #pragma unroll 8
        for (int c = 0; c < 128; c++) {
            float v = sF[row*132 + c];
            sum += v; sq += v*v;
        }
        const float mu = sum * (1.0f/128.0f);
        const float istd = rsqrtf(sq*(1.0f/128.0f) - mu*mu + 1e-5f);

        const int n = base + row;
        const int s = n % S_;
        const int bm = n / S_;
        float* op = d_out + (((s*B_ + (bm >> 3))*M_ + (bm & 7)) << 7);
        #pragma unroll 4
        for (int c = 0; c < 128; c += 4) {
            float4 o4;
            o4.x = (sF[row*132+c+0]-mu)*istd*__ldg(&ln2_g[c+0]) + __ldg(&ln2_b[c+0]);
            o4.y = (sF[row*132+c+1]-mu)*istd*__ldg(&ln2_g[c+1]) + __ldg(&ln2_b[c+1]);
            o4.z = (sF[row*132+c+2]-mu)*istd*__ldg(&ln2_g[c+2]) + __ldg(&ln2_b[c+2]);
            o4.w = (sF[row*132+c+3]-mu)*istd*__ldg(&ln2_g[c+3]) + __ldg(&ln2_b[c+3]);
            *reinterpret_cast<float4*>(op + c) = o4;
        }
    }
}

// ================= kernel 4: seg_mask all_seg fix =================
__global__ void k_maskfix(float* __restrict__ d_out)
{
    const int t = threadIdx.x;   // 128 = B*M
    float allm = 1.0f;
    for (int s = 0; s < S_; s++) allm = fminf(allm, d_out[OUT_ELEMS + t*S_ + s]);
    if (allm > 0.5f) d_out[OUT_ELEMS + t*S_] = 0.0f;
}

// ================= launcher =================
extern "C" void kernel_launch(void* const* d_in, const int* in_sizes, int n_in,
                              void* d_out, int out_size)
{
    const float* roads  = (const float*)d_in[0];
    const float* ms     = (const float*)d_in[2];
    const float* lin_w  = (const float*)d_in[3];
    const float* lin_b  = (const float*)d_in[4];
    const float* wq     = (const float*)d_in[5];
    const float* wk     = (const float*)d_in[6];
    const float* wv     = (const float*)d_in[7];
    const float* bq     = (const float*)d_in[8];
    const float* bk     = (const float*)d_in[9];
    const float* bv     = (const float*)d_in[10];
    const float* out_w  = (const float*)d_in[11];
    const float* out_b  = (const float*)d_in[12];
    const float* ln1_g  = (const float*)d_in[13];
    const float* ln1_b  = (const float*)d_in[14];
    const float* w1     = (const float*)d_in[15];
    const float* b1     = (const float*)d_in[16];
    const float* w2     = (const float*)d_in[17];
    const float* b2     = (const float*)d_in[18];
    const float* ln2_g  = (const float*)d_in[19];
    const float* ln2_b  = (const float*)d_in[20];
    float* out = (float*)d_out;

    cudaFuncSetAttribute(k_ffn_mma, cudaFuncAttributeMaxDynamicSharedMemorySize, K3_DSMEM);

    k_pre<<<1, 128>>>(ms, lin_w, lin_b, wq, wk, wv, bq, bk, bv, out_w, out_b);
    k_prew<<<6, 256>>>(w1, w2);
    k_attn<<<N_SEG/8, 256>>>(roads, ln1_g, ln1_b, out);
    k_maskfix<<<1, 128>>>(out);
    k_ffn_mma<<<N_SEG/128, 256, K3_DSMEM>>>(b1, b2, ln2_g, ln2_b, out);
}

// round 4
// speedup vs baseline: 1.7612x; 1.1461x over previous
#include <cuda_runtime.h>
#include <cuda_bf16.h>
#include <math.h>
#include <stdint.h>

#define N_SEG 12800
#define D_ 128
#define S_ 100
#define B_ 16
#define M_ 8
#define P_ 40
#define OUT_ELEMS (S_*B_*M_*D_)   // 1638400
#define FULLMASK 0xffffffffu

// padded row stride for all smem/global bf16 tiles (bank-conflict-free frags)
#define LDT 136
#define TILE_E (128*LDT)          // elems per 128x128 padded tile (17408)
#define T_BYTES (TILE_E*2)        // 34816

// ---------------- precomputed folded weights ----------------
__device__ float g_score_w[24];     // [a*8+h]
__device__ float g_score_c[8];
__device__ float g_W2[24*128];      // [(h*3+a)*128 + j]
__device__ float g_c2[128];
__device__ float g_emb[N_SEG*D_];   // post-LN1 embeddings (6.5MB scratch)

// pre-split bf16 weight tiles, padded [n][LDT]:
// tile pair w: [hi, lo] contiguous. w=0..2: w1 n-chunks, w=3..5: w2 k-chunks
__device__ __align__(16) __nv_bfloat16 g_wb[6*2*TILE_E];

__device__ __forceinline__ unsigned pk2(float a, float b) {
    __nv_bfloat162 t = __floats2bfloat162_rn(a, b);
    return *reinterpret_cast<unsigned*>(&t);
}
__device__ __forceinline__ float blo(float x) {
    return x - __bfloat162float(__float2bfloat16(x));
}
__device__ __forceinline__ void mma16816(float* c, const uint32_t* a, uint32_t b0, uint32_t b1) {
    asm volatile("mma.sync.aligned.m16n8k16.row.col.f32.bf16.bf16.f32 "
        "{%0,%1,%2,%3}, {%4,%5,%6,%7}, {%8,%9}, {%0,%1,%2,%3};"
        : "+f"(c[0]), "+f"(c[1]), "+f"(c[2]), "+f"(c[3])
        : "r"(a[0]), "r"(a[1]), "r"(a[2]), "r"(a[3]), "r"(b0), "r"(b1));
}
__device__ __forceinline__ void ldsm4(uint32_t* r, uint32_t addr) {
    asm volatile("ldmatrix.sync.aligned.m8n8.x4.shared.b16 {%0,%1,%2,%3}, [%4];"
        : "=r"(r[0]), "=r"(r[1]), "=r"(r[2]), "=r"(r[3]) : "r"(addr));
}
__device__ __forceinline__ void cpa16(uint32_t daddr, const void* g) {
    asm volatile("cp.async.cg.shared.global [%0], [%1], 16;" :: "r"(daddr), "l"(g));
}
__device__ __forceinline__ void cpa_wait() {
    asm volatile("cp.async.commit_group;\ncp.async.wait_group 0;" ::: "memory");
}

// ================= kernel 1: fold weights + split FFN weights (7 blocks) =================
__global__ void k_pre7(const float* __restrict__ ms,   const float* __restrict__ lin_w,
                       const float* __restrict__ lin_b,const float* __restrict__ wq,
                       const float* __restrict__ wk,   const float* __restrict__ wv,
                       const float* __restrict__ bq,   const float* __restrict__ bk,
                       const float* __restrict__ bv,   const float* __restrict__ out_w,
                       const float* __restrict__ out_b,
                       const float* __restrict__ w1,   const float* __restrict__ w2)
{
    if (blockIdx.x < 6) {
        // -------- split FFN weights to padded bf16 hi/lo --------
        const int w = blockIdx.x;
        __nv_bfloat16* dh = g_wb + (w*2+0)*TILE_E;
        __nv_bfloat16* dl = g_wb + (w*2+1)*TILE_E;
        for (int i = threadIdx.x; i < 128*128; i += 256) {
            int n = i >> 7, k = i & 127;
            float v = (w < 3) ? w1[k*384 + w*128 + n]
                              : w2[((w-3)*128 + k)*128 + n];
            __nv_bfloat16 h = __float2bfloat16(v);
            dh[n*LDT + k] = h;
            dl[n*LDT + k] = __float2bfloat16(v - __bfloat162float(h));
        }
        return;
    }
    // -------- fold attention weights (block 6, threads 0..127) --------
    __shared__ float q[128];
    __shared__ float wkq[128*8];
    __shared__ float lwv[3*128];
    __shared__ float cv[128];
    const int t = threadIdx.x;
    if (t >= 128) return;

    {
        float acc = bq[t];
        for (int e = 0; e < 128; e++) acc += ms[e]*wq[e*128+t];
        q[t] = acc;
    }
    __syncthreads();

    #pragma unroll
    for (int h = 0; h < 8; h++) {
        float s = 0.f;
        #pragma unroll
        for (int j = 0; j < 16; j++) s += wk[t*128 + h*16 + j]*q[h*16 + j];
        wkq[t*8 + h] = s;
    }
    __syncthreads();

    if (t < 24) {
        int a = t/8, h = t%8;
        float s = 0.f;
        for (int d = 0; d < 128; d++) s += lin_w[a*128+d]*wkq[d*8+h];
        g_score_w[a*8+h] = 0.25f*s;
    } else if (t < 32) {
        int h = t-24;
        float s = 0.f;
        for (int d = 0; d < 128; d++) s += lin_b[d]*wkq[d*8+h];
        for (int j = 0; j < 16; j++) s += q[h*16+j]*bk[h*16+j];
        g_score_c[h] = 0.25f*s;
    }

    {
        float s0=0.f, s1=0.f, s2=0.f, sc=0.f;
        for (int e = 0; e < 128; e++) {
            float w = wv[e*128 + t];
            s0 += lin_w[0*128+e]*w;
            s1 += lin_w[1*128+e]*w;
            s2 += lin_w[2*128+e]*w;
            sc += lin_b[e]*w;
        }
        lwv[0*128+t]=s0; lwv[1*128+t]=s1; lwv[2*128+t]=s2;
        cv[t] = sc + bv[t];
    }
    __syncthreads();

    #pragma unroll
    for (int h = 0; h < 8; h++)
        #pragma unroll
        for (int a = 0; a < 3; a++) {
            float s = 0.f;
            #pragma unroll
            for (int dd = 0; dd < 16; dd++) {
                int d = h*16 + dd;
                s += lwv[a*128+d]*out_w[d*128+t];
            }
            g_W2[(h*3+a)*128 + t] = s;
        }
    {
        float s = out_b[t];
        for (int d = 0; d < 128; d++) s += cv[d]*out_w[d*128+t];
        g_c2[t] = s;
    }
}

// ================= kernel 2: attention pooling + LN1 =================
__global__ void k_attn(const float* __restrict__ roads,
                       const float* __restrict__ ln1_g, const float* __restrict__ ln1_b,
                       float* __restrict__ d_out)
{
    const int n    = (blockIdx.x*blockDim.x + threadIdx.x) >> 5;
    const int lane = threadIdx.x & 31;
    if (n >= N_SEG) return;

    const float4* rp = reinterpret_cast<const float4*>(roads) + n*P_;
    float4 a0 = rp[lane];
    float4 a1 = make_float4(0.f,0.f,0.f,0.f);
    if (lane < 8) a1 = rp[32 + lane];

    bool v0 = (a0.w != 0.0f);
    bool v1 = (lane < 8) && (a1.w != 0.0f);
    unsigned bm0 = __ballot_sync(FULLMASK, v0);
    unsigned bm1 = __ballot_sync(FULLMASK, v1);
    const bool seg_empty = ((bm0 | bm1) == 0u);
    if (seg_empty && lane == 0) v0 = true;

    float pa[24];
    #pragma unroll
    for (int h = 0; h < 8; h++) {
        const float sw0 = __ldg(&g_score_w[0*8+h]);
        const float sw1 = __ldg(&g_score_w[1*8+h]);
        const float sw2 = __ldg(&g_score_w[2*8+h]);
        const float sc  = __ldg(&g_score_c[h]);
        float s0 = sc + a0.x*sw0 + a0.y*sw1 + a0.z*sw2;
        float s1 = sc + a1.x*sw0 + a1.y*sw1 + a1.z*sw2;
        float mx = fmaxf(v0 ? s0 : -1e30f, v1 ? s1 : -1e30f);
        #pragma unroll
        for (int o = 16; o; o >>= 1) mx = fmaxf(mx, __shfl_xor_sync(FULLMASK, mx, o));
        float e0 = v0 ? __expf(s0 - mx) : 0.0f;
        float e1 = v1 ? __expf(s1 - mx) : 0.0f;
        float t0 = e0 + e1;
        float t1 = e0*a0.x + e1*a1.x;
        float t2 = e0*a0.y + e1*a1.y;
        float t3 = e0*a0.z + e1*a1.z;
        #pragma unroll
        for (int o = 16; o; o >>= 1) {
            t0 += __shfl_xor_sync(FULLMASK, t0, o);
            t1 += __shfl_xor_sync(FULLMASK, t1, o);
            t2 += __shfl_xor_sync(FULLMASK, t2, o);
            t3 += __shfl_xor_sync(FULLMASK, t3, o);
        }
        float inv = 1.0f / t0;
        pa[h*3+0] = t1*inv;
        pa[h*3+1] = t2*inv;
        pa[h*3+2] = t3*inv;
    }

    float y[4];
    #pragma unroll
    for (int u = 0; u < 4; u++) {
        int j = lane + 32*u;
        float acc = __ldg(&g_c2[j]);
        #pragma unroll
        for (int i = 0; i < 24; i++) acc += pa[i]*__ldg(&g_W2[i*128 + j]);
        y[u] = acc;
    }

    float loc = y[0]+y[1]+y[2]+y[3];
    #pragma unroll
    for (int o = 16; o; o >>= 1) loc += __shfl_xor_sync(FULLMASK, loc, o);
    const float mu = loc * (1.0f/128.0f);
    float sq = 0.f;
    #pragma unroll
    for (int u = 0; u < 4; u++) { float d = y[u]-mu; sq += d*d; }
    #pragma unroll
    for (int o = 16; o; o >>= 1) sq += __shfl_xor_sync(FULLMASK, sq, o);
    const float istd = rsqrtf(sq*(1.0f/128.0f) + 1e-5f);
    #pragma unroll
    for (int u = 0; u < 4; u++) {
        int j = lane + 32*u;
        g_emb[n*128 + j] = (y[u]-mu)*istd*__ldg(&ln1_g[j]) + __ldg(&ln1_b[j]);
    }

    if (lane == 0) d_out[OUT_ELEMS + n] = seg_empty ? 1.0f : 0.0f;
}

// ================= kernel 3: HMMA split-bf16 FFN (ldmatrix) + residual + LN2 =================
// grid=100, block=256 (8 warps: 4 m-groups x 2 n-groups, warp tile m32 x n64)
#define K3_DSMEM (6*T_BYTES)    // 208896

// one gemm pass via ldmatrix: acc += A[m32][k128] * Bt[n64][k128]^T
// aB/bB: per-thread smem byte addresses (include lane offsets and m/n base)
__device__ __forceinline__ void gemm_pass(uint32_t aB, uint32_t bB, float (&acc)[2][8][4])
{
    #pragma unroll
    for (int k = 0; k < 8; k++) {
        uint32_t a0[4], a1[4];
        ldsm4(a0, aB + k*32);
        ldsm4(a1, aB + 16*LDT*2 + k*32);
        #pragma unroll
        for (int ntp = 0; ntp < 4; ntp++) {
            uint32_t b[4];
            ldsm4(b, bB + ntp*16*LDT*2 + k*32);
            mma16816(acc[0][2*ntp+0], a0, b[0], b[1]);
            mma16816(acc[1][2*ntp+0], a1, b[0], b[1]);
            mma16816(acc[0][2*ntp+1], a0, b[2], b[3]);
            mma16816(acc[1][2*ntp+1], a1, b[2], b[3]);
        }
    }
}

__global__ __launch_bounds__(256, 1)
void k_ffn_mma(const float* __restrict__ b1, const float* __restrict__ b2,
               const float* __restrict__ ln2_g, const float* __restrict__ ln2_b,
               float* __restrict__ d_out)
{
    extern __shared__ __align__(16) char smem[];
    __nv_bfloat16* sAh = reinterpret_cast<__nv_bfloat16*>(smem);
    __nv_bfloat16* sAl = sAh + TILE_E;
    __nv_bfloat16* sHh = sAl + TILE_E;
    __nv_bfloat16* sHl = sHh + TILE_E;
    __nv_bfloat16* sBh = sHl + TILE_E;

    const uint32_t sb  = (uint32_t)__cvta_generic_to_shared(smem);
    const uint32_t AH = sb, AL = AH + T_BYTES, HHp = AL + T_BYTES,
                   HL = HHp + T_BYTES, BH = HL + T_BYTES, BL = BH + T_BYTES;

    const int tid  = threadIdx.x;
    const int wid  = tid >> 5;
    const int lane = tid & 31;
    const int qr   = lane >> 2;          // 0..7
    const int qc   = (lane & 3) << 1;    // 0,2,4,6
    const int mbase = (wid >> 1) * 32;
    const int nbase = (wid & 1) * 64;
    const int base  = blockIdx.x * 128;

    // per-thread ldmatrix lane offsets (bytes)
    const uint32_t aoff = (uint32_t)(((lane & 15)*LDT + (lane >> 4)*8)*2 + mbase*LDT*2);
    const uint32_t boff = (uint32_t)((((lane & 7) + ((lane >> 4) << 3))*LDT
                                      + ((lane >> 3) & 1)*8)*2 + nbase*LDT*2);

    // ---- issue W1(0) staging via cp.async (hi+lo contiguous 69632B) ----
    {
        const char* src = reinterpret_cast<const char*>(g_wb);
        for (int i = tid; i < 2*T_BYTES/16; i += 256)
            cpa16(BH + i*16, src + i*16);
    }

    // ---- block 0: seg_mask all_seg fix (after k_attn, overlapped) ----
    if (blockIdx.x == 0 && tid < 128) {
        float allm = 1.0f;
        #pragma unroll 4
        for (int s = 0; s < S_; s++)
            allm = fminf(allm, d_out[OUT_ELEMS + tid*S_ + s]);
        if (allm > 0.5f) d_out[OUT_ELEMS + tid*S_] = 0.0f;
    }

    // ---- stage A = emb tile (bf16 hi/lo) ----
    {
        const float4* eb = reinterpret_cast<const float4*>(g_emb + base*128);
        for (int i = tid; i < 4096; i += 256) {
            int r = i >> 5, c4 = (i & 31) << 2;
            float4 v = eb[i];
            int off = r*LDT + c4;
            *reinterpret_cast<uint2*>(sAh + off) = make_uint2(pk2(v.x,v.y), pk2(v.z,v.w));
            *reinterpret_cast<uint2*>(sAl + off) =
                make_uint2(pk2(blo(v.x),blo(v.y)), pk2(blo(v.z),blo(v.w)));
        }
    }
    cpa_wait();
    __syncthreads();

    float acc2[2][8][4];
    #pragma unroll
    for (int mt = 0; mt < 2; mt++)
        #pragma unroll
        for (int nt = 0; nt < 8; nt++)
            #pragma unroll
            for (int c = 0; c < 4; c++) acc2[mt][nt][c] = 0.f;

    for (int kc = 0; kc < 3; kc++) {
        // ---- layer1: acc1 = A @ W1c (3 passes) ----
        float acc1[2][8][4];
        #pragma unroll
        for (int mt = 0; mt < 2; mt++)
            #pragma unroll
            for (int nt = 0; nt < 8; nt++)
                #pragma unroll
                for (int c = 0; c < 4; c++) acc1[mt][nt][c] = 0.f;
        gemm_pass(AH + aoff, BH + boff, acc1);
        gemm_pass(AH + aoff, BL + boff, acc1);
        gemm_pass(AL + aoff, BH + boff, acc1);

        // ---- relu + bias + split -> sH ----
        #pragma unroll
        for (int mt = 0; mt < 2; mt++)
            #pragma unroll
            for (int nt = 0; nt < 8; nt++) {
                const int row = mbase + mt*16 + qr;
                const int col = nbase + nt*8 + qc;
                const int cg  = kc*128 + col;
                float v0 = fmaxf(acc1[mt][nt][0] + __ldg(&b1[cg]),   0.f);
                float v1 = fmaxf(acc1[mt][nt][1] + __ldg(&b1[cg+1]), 0.f);
                float v2 = fmaxf(acc1[mt][nt][2] + __ldg(&b1[cg]),   0.f);
                float v3 = fmaxf(acc1[mt][nt][3] + __ldg(&b1[cg+1]), 0.f);
                *reinterpret_cast<uint32_t*>(sHh + row*LDT + col)     = pk2(v0, v1);
                *reinterpret_cast<uint32_t*>(sHl + row*LDT + col)     = pk2(blo(v0), blo(v1));
                *reinterpret_cast<uint32_t*>(sHh + (row+8)*LDT + col) = pk2(v2, v3);
                *reinterpret_cast<uint32_t*>(sHl + (row+8)*LDT + col) = pk2(blo(v2), blo(v3));
            }
        __syncthreads();   // H visible, B buffer free

        // ---- stage W2(kc) ----
        {
            const char* src = reinterpret_cast<const char*>(g_wb + (3+kc)*2*TILE_E);
            for (int i = tid; i < 2*T_BYTES/16; i += 256)
                cpa16(BH + i*16, src + i*16);
        }
        cpa_wait();
        __syncthreads();

        // ---- layer2 partial: acc2 += Hc @ W2c (3 passes) ----
        gemm_pass(HHp + aoff, BH + boff, acc2);
        gemm_pass(HHp + aoff, BL + boff, acc2);
        gemm_pass(HL  + aoff, BH + boff, acc2);

        if (kc < 2) {
            __syncthreads();   // B free
            const char* src = reinterpret_cast<const char*>(g_wb + (kc+1)*2*TILE_E);
            for (int i = tid; i < 2*T_BYTES/16; i += 256)
                cpa16(BH + i*16, src + i*16);
            cpa_wait();
            __syncthreads();
        }
    }
    __syncthreads();

    // ---- dump acc2 + bias + residual to f32 smem buffer [128][132] ----
    float* sF = reinterpret_cast<float*>(smem);
    #pragma unroll
    for (int mt = 0; mt < 2; mt++)
        #pragma unroll
        for (int nt = 0; nt < 8; nt++) {
            const int row = mbase + mt*16 + qr;
            const int col = nbase + nt*8 + qc;
            const float2 e0 = *reinterpret_cast<const float2*>(&g_emb[(base+row)*128 + col]);
            const float2 e1 = *reinterpret_cast<const float2*>(&g_emb[(base+row+8)*128 + col]);
            const float bb0 = __ldg(&b2[col]), bb1 = __ldg(&b2[col+1]);
            sF[row*132 + col]       = acc2[mt][nt][0] + bb0 + e0.x;
            sF[row*132 + col + 1]   = acc2[mt][nt][1] + bb1 + e0.y;
            sF[(row+8)*132 + col]   = acc2[mt][nt][2] + bb0 + e1.x;
            sF[(row+8)*132 + col+1] = acc2[mt][nt][3] + bb1 + e1.y;
        }
    __syncthreads();

    // ---- LN2 + transposed store ----
    if (tid < 128) {
        const int row = tid;
        float sum = 0.f, sq = 0.f;
        #pragma unroll 8
        for (int c = 0; c < 128; c++) {
            float v = sF[row*132 + c];
            sum += v; sq += v*v;
        }
        const float mu = sum * (1.0f/128.0f);
        const float istd = rsqrtf(sq*(1.0f/128.0f) - mu*mu + 1e-5f);

        const int n = base + row;
        const int s = n % S_;
        const int bm = n / S_;
        float* op = d_out + (((s*B_ + (bm >> 3))*M_ + (bm & 7)) << 7);
        #pragma unroll 4
        for (int c = 0; c < 128; c += 4) {
            float4 o4;
            o4.x = (sF[row*132+c+0]-mu)*istd*__ldg(&ln2_g[c+0]) + __ldg(&ln2_b[c+0]);
            o4.y = (sF[row*132+c+1]-mu)*istd*__ldg(&ln2_g[c+1]) + __ldg(&ln2_b[c+1]);
            o4.z = (sF[row*132+c+2]-mu)*istd*__ldg(&ln2_g[c+2]) + __ldg(&ln2_b[c+2]);
            o4.w = (sF[row*132+c+3]-mu)*istd*__ldg(&ln2_g[c+3]) + __ldg(&ln2_b[c+3]);
            *reinterpret_cast<float4*>(op + c) = o4;
        }
    }
}

// ================= launcher =================
extern "C" void kernel_launch(void* const* d_in, const int* in_sizes, int n_in,
                              void* d_out, int out_size)
{
    const float* roads  = (const float*)d_in[0];
    const float* ms     = (const float*)d_in[2];
    const float* lin_w  = (const float*)d_in[3];
    const float* lin_b  = (const float*)d_in[4];
    const float* wq     = (const float*)d_in[5];
    const float* wk     = (const float*)d_in[6];
    const float* wv     = (const float*)d_in[7];
    const float* bq     = (const float*)d_in[8];
    const float* bk     = (const float*)d_in[9];
    const float* bv     = (const float*)d_in[10];
    const float* out_w  = (const float*)d_in[11];
    const float* out_b  = (const float*)d_in[12];
    const float* ln1_g  = (const float*)d_in[13];
    const float* ln1_b  = (const float*)d_in[14];
    const float* w1     = (const float*)d_in[15];
    const float* b1     = (const float*)d_in[16];
    const float* w2     = (const float*)d_in[17];
    const float* b2     = (const float*)d_in[18];
    const float* ln2_g  = (const float*)d_in[19];
    const float* ln2_b  = (const float*)d_in[20];
    float* out = (float*)d_out;

    cudaFuncSetAttribute(k_ffn_mma, cudaFuncAttributeMaxDynamicSharedMemorySize, K3_DSMEM);

    k_pre7<<<7, 256>>>(ms, lin_w, lin_b, wq, wk, wv, bq, bk, bv, out_w, out_b, w1, w2);
    k_attn<<<N_SEG/8, 256>>>(roads, ln1_g, ln1_b, out);
    k_ffn_mma<<<N_SEG/128, 256, K3_DSMEM>>>(b1, b2, ln2_g, ln2_b, out);
}

// round 5
// speedup vs baseline: 1.9958x; 1.1332x over previous
#include <cuda_runtime.h>
#include <cuda_bf16.h>
#include <math.h>
#include <stdint.h>

#define N_SEG 12800
#define D_ 128
#define S_ 100
#define B_ 16
#define M_ 8
#define P_ 40
#define OUT_ELEMS (S_*B_*M_*D_)   // 1638400
#define FULLMASK 0xffffffffu

// padded row stride for all smem/global bf16 tiles (bank-conflict-free frags)
#define LDT 136
#define TILE_E (128*LDT)          // elems per 128x128 padded tile (17408)
#define T_BYTES (TILE_E*2)        // 34816

// ---------------- precomputed folded weights ----------------
__device__ float g_score_w[24];     // [a*8+h]
__device__ float g_score_c[8];
__device__ float g_W2[24*128];      // [(h*3+a)*128 + j]
__device__ float g_c2[128];
__device__ float g_emb[N_SEG*D_];   // post-LN1 embeddings (6.5MB scratch)

// pre-split bf16 weight tiles, padded [n][LDT]:
// tile pair w: [hi, lo] contiguous. w=0..2: w1 n-chunks, w=3..5: w2 k-chunks
__device__ __align__(16) __nv_bfloat16 g_wb[6*2*TILE_E];

__device__ __forceinline__ unsigned pk2(float a, float b) {
    __nv_bfloat162 t = __floats2bfloat162_rn(a, b);
    return *reinterpret_cast<unsigned*>(&t);
}
__device__ __forceinline__ float blo(float x) {
    return x - __bfloat162float(__float2bfloat16(x));
}
__device__ __forceinline__ void mma16816(float* c, const uint32_t* a, uint32_t b0, uint32_t b1) {
    asm volatile("mma.sync.aligned.m16n8k16.row.col.f32.bf16.bf16.f32 "
        "{%0,%1,%2,%3}, {%4,%5,%6,%7}, {%8,%9}, {%0,%1,%2,%3};"
        : "+f"(c[0]), "+f"(c[1]), "+f"(c[2]), "+f"(c[3])
        : "r"(a[0]), "r"(a[1]), "r"(a[2]), "r"(a[3]), "r"(b0), "r"(b1));
}
__device__ __forceinline__ void ldsm4(uint32_t* r, uint32_t addr) {
    asm volatile("ldmatrix.sync.aligned.m8n8.x4.shared.b16 {%0,%1,%2,%3}, [%4];"
        : "=r"(r[0]), "=r"(r[1]), "=r"(r[2]), "=r"(r[3]) : "r"(addr));
}
__device__ __forceinline__ void cpa16(uint32_t daddr, const void* g) {
    asm volatile("cp.async.cg.shared.global [%0], [%1], 16;" :: "r"(daddr), "l"(g));
}
__device__ __forceinline__ void cpa_wait() {
    asm volatile("cp.async.commit_group;\ncp.async.wait_group 0;" ::: "memory");
}

// ================= kernel 1: fold weights + split FFN weights (7 blocks) =================
// dynamic smem: 64KB staging buffer for one 128x128 weight matrix
#define PRE_DSMEM (64*1024)

__global__ void k_pre7(const float* __restrict__ ms,   const float* __restrict__ lin_w,
                       const float* __restrict__ lin_b,const float* __restrict__ wq,
                       const float* __restrict__ wk,   const float* __restrict__ wv,
                       const float* __restrict__ bq,   const float* __restrict__ bk,
                       const float* __restrict__ bv,   const float* __restrict__ out_w,
                       const float* __restrict__ out_b,
                       const float* __restrict__ w1,   const float* __restrict__ w2)
{
    if (blockIdx.x < 6) {
        // -------- split FFN weights to padded bf16 hi/lo (vectorized reads) --------
        const int w = blockIdx.x;
        __nv_bfloat16* dh = g_wb + (w*2+0)*TILE_E;
        __nv_bfloat16* dl = g_wb + (w*2+1)*TILE_E;
        for (int i = threadIdx.x; i < 128*32; i += 256) {
            // i indexes a float4 of k for row n
            int n = i >> 5, k4 = (i & 31) << 2;
            float4 v = (w < 3)
                ? make_float4(w1[(k4+0)*384 + w*128 + n], w1[(k4+1)*384 + w*128 + n],
                              w1[(k4+2)*384 + w*128 + n], w1[(k4+3)*384 + w*128 + n])
                : make_float4(w2[((w-3)*128 + k4+0)*128 + n], w2[((w-3)*128 + k4+1)*128 + n],
                              w2[((w-3)*128 + k4+2)*128 + n], w2[((w-3)*128 + k4+3)*128 + n]);
            __nv_bfloat16 h0 = __float2bfloat16(v.x), h1 = __float2bfloat16(v.y);
            __nv_bfloat16 h2 = __float2bfloat16(v.z), h3 = __float2bfloat16(v.w);
            int off = n*LDT + k4;
            *reinterpret_cast<uint2*>(dh + off) = make_uint2(
                (uint32_t)*(uint16_t*)&h0 | ((uint32_t)*(uint16_t*)&h1 << 16),
                (uint32_t)*(uint16_t*)&h2 | ((uint32_t)*(uint16_t*)&h3 << 16));
            *reinterpret_cast<uint2*>(dl + off) = make_uint2(
                pk2(v.x - __bfloat162float(h0), v.y - __bfloat162float(h1)),
                pk2(v.z - __bfloat162float(h2), v.w - __bfloat162float(h3)));
        }
        return;
    }

    // -------- fold attention weights (block 6, 256 threads, smem-staged) --------
    extern __shared__ float W[];        // 16384 floats = one 128x128 matrix
    __shared__ float q[128];
    __shared__ float wkq[128*8];
    __shared__ float lwv[3*128];
    __shared__ float cv[128];
    __shared__ float ms_s[128], lb_s[128];
    const int t = threadIdx.x;

    // small vectors
    if (t < 128) { ms_s[t] = ms[t]; lb_s[t] = lin_b[t]; }

    // ---- stage wq -> W ; q = ms@wq + bq ----
    {
        const float4* src = reinterpret_cast<const float4*>(wq);
        float4* dst = reinterpret_cast<float4*>(W);
        #pragma unroll
        for (int i = 0; i < 16; i++) dst[t + 256*i] = src[t + 256*i];
    }
    __syncthreads();
    if (t < 128) {
        float acc = bq[t];
        #pragma unroll 8
        for (int e = 0; e < 128; e++) acc += ms_s[e]*W[e*128+t];
        q[t] = acc;
    }
    __syncthreads();

    // ---- stage wk -> W ; wkq[d][h] ----
    {
        const float4* src = reinterpret_cast<const float4*>(wk);
        float4* dst = reinterpret_cast<float4*>(W);
        #pragma unroll
        for (int i = 0; i < 16; i++) dst[t + 256*i] = src[t + 256*i];
    }
    __syncthreads();
    if (t < 128) {
        #pragma unroll
        for (int h = 0; h < 8; h++) {
            float s = 0.f;
            #pragma unroll
            for (int j = 0; j < 16; j++) s += W[t*128 + h*16 + j]*q[h*16 + j];
            wkq[t*8 + h] = s;
        }
    }
    __syncthreads();

    if (t < 24) {
        int a = t/8, h = t%8;
        float s = 0.f;
        #pragma unroll 8
        for (int d = 0; d < 128; d++) s += lin_w[a*128+d]*wkq[d*8+h];
        g_score_w[a*8+h] = 0.25f*s;
    } else if (t < 32) {
        int h = t-24;
        float s = 0.f;
        #pragma unroll 8
        for (int d = 0; d < 128; d++) s += lb_s[d]*wkq[d*8+h];
        #pragma unroll
        for (int j = 0; j < 16; j++) s += q[h*16+j]*bk[h*16+j];
        g_score_c[h] = 0.25f*s;
    }

    // ---- stage wv -> W ; lwv, cv ----
    {
        const float4* src = reinterpret_cast<const float4*>(wv);
        float4* dst = reinterpret_cast<float4*>(W);
        #pragma unroll
        for (int i = 0; i < 16; i++) dst[t + 256*i] = src[t + 256*i];
    }
    __syncthreads();
    if (t < 128) {
        float s0=0.f, s1=0.f, s2=0.f, sc=0.f;
        #pragma unroll 8
        for (int e = 0; e < 128; e++) {
            float w = W[e*128 + t];
            s0 += lin_w[0*128+e]*w;
            s1 += lin_w[1*128+e]*w;
            s2 += lin_w[2*128+e]*w;
            sc += lb_s[e]*w;
        }
        lwv[0*128+t]=s0; lwv[1*128+t]=s1; lwv[2*128+t]=s2;
        cv[t] = sc + bv[t];
    }
    __syncthreads();

    // ---- stage out_w -> W ; W2, c2 ----
    {
        const float4* src = reinterpret_cast<const float4*>(out_w);
        float4* dst = reinterpret_cast<float4*>(W);
        #pragma unroll
        for (int i = 0; i < 16; i++) dst[t + 256*i] = src[t + 256*i];
    }
    __syncthreads();
    if (t < 128) {
        #pragma unroll
        for (int h = 0; h < 8; h++)
            #pragma unroll
            for (int a = 0; a < 3; a++) {
                float s = 0.f;
                #pragma unroll
                for (int dd = 0; dd < 16; dd++) {
                    int d = h*16 + dd;
                    s += lwv[a*128+d]*W[d*128+t];
                }
                g_W2[(h*3+a)*128 + t] = s;
            }
        float s = out_b[t];
        #pragma unroll 8
        for (int d = 0; d < 128; d++) s += cv[d]*W[d*128+t];
        g_c2[t] = s;
    }
}

// ================= kernel 2: attention pooling + LN1 =================
__global__ void k_attn(const float* __restrict__ roads,
                       const float* __restrict__ ln1_g, const float* __restrict__ ln1_b,
                       float* __restrict__ d_out)
{
    const int n    = (blockIdx.x*blockDim.x + threadIdx.x) >> 5;
    const int lane = threadIdx.x & 31;
    if (n >= N_SEG) return;

    const float4* rp = reinterpret_cast<const float4*>(roads) + n*P_;
    float4 a0 = rp[lane];
    float4 a1 = make_float4(0.f,0.f,0.f,0.f);
    if (lane < 8) a1 = rp[32 + lane];

    bool v0 = (a0.w != 0.0f);
    bool v1 = (lane < 8) && (a1.w != 0.0f);
    unsigned bm0 = __ballot_sync(FULLMASK, v0);
    unsigned bm1 = __ballot_sync(FULLMASK, v1);
    const bool seg_empty = ((bm0 | bm1) == 0u);
    if (seg_empty && lane == 0) v0 = true;

    float pa[24];
    #pragma unroll
    for (int h = 0; h < 8; h++) {
        const float sw0 = __ldg(&g_score_w[0*8+h]);
        const float sw1 = __ldg(&g_score_w[1*8+h]);
        const float sw2 = __ldg(&g_score_w[2*8+h]);
        const float sc  = __ldg(&g_score_c[h]);
        float s0 = sc + a0.x*sw0 + a0.y*sw1 + a0.z*sw2;
        float s1 = sc + a1.x*sw0 + a1.y*sw1 + a1.z*sw2;
        float mx = fmaxf(v0 ? s0 : -1e30f, v1 ? s1 : -1e30f);
        #pragma unroll
        for (int o = 16; o; o >>= 1) mx = fmaxf(mx, __shfl_xor_sync(FULLMASK, mx, o));
        float e0 = v0 ? __expf(s0 - mx) : 0.0f;
        float e1 = v1 ? __expf(s1 - mx) : 0.0f;
        float t0 = e0 + e1;
        float t1 = e0*a0.x + e1*a1.x;
        float t2 = e0*a0.y + e1*a1.y;
        float t3 = e0*a0.z + e1*a1.z;
        #pragma unroll
        for (int o = 16; o; o >>= 1) {
            t0 += __shfl_xor_sync(FULLMASK, t0, o);
            t1 += __shfl_xor_sync(FULLMASK, t1, o);
            t2 += __shfl_xor_sync(FULLMASK, t2, o);
            t3 += __shfl_xor_sync(FULLMASK, t3, o);
        }
        float inv = 1.0f / t0;
        pa[h*3+0] = t1*inv;
        pa[h*3+1] = t2*inv;
        pa[h*3+2] = t3*inv;
    }

    float y[4];
    #pragma unroll
    for (int u = 0; u < 4; u++) {
        int j = lane + 32*u;
        float acc = __ldg(&g_c2[j]);
        #pragma unroll
        for (int i = 0; i < 24; i++) acc += pa[i]*__ldg(&g_W2[i*128 + j]);
        y[u] = acc;
    }

    float loc = y[0]+y[1]+y[2]+y[3];
    #pragma unroll
    for (int o = 16; o; o >>= 1) loc += __shfl_xor_sync(FULLMASK, loc, o);
    const float mu = loc * (1.0f/128.0f);
    float sq = 0.f;
    #pragma unroll
    for (int u = 0; u < 4; u++) { float d = y[u]-mu; sq += d*d; }
    #pragma unroll
    for (int o = 16; o; o >>= 1) sq += __shfl_xor_sync(FULLMASK, sq, o);
    const float istd = rsqrtf(sq*(1.0f/128.0f) + 1e-5f);
    #pragma unroll
    for (int u = 0; u < 4; u++) {
        int j = lane + 32*u;
        g_emb[n*128 + j] = (y[u]-mu)*istd*__ldg(&ln1_g[j]) + __ldg(&ln1_b[j]);
    }

    if (lane == 0) d_out[OUT_ELEMS + n] = seg_empty ? 1.0f : 0.0f;
}

// ================= kernel 3: HMMA split-bf16 FFN (ldmatrix) + residual + LN2 =================
// grid=100, block=256 (8 warps: 4 m-groups x 2 n-groups, warp tile m32 x n64)
#define K3_DSMEM (6*T_BYTES)    // 208896

// one gemm pass via ldmatrix: acc += A[m32][k128] * Bt[n64][k128]^T
__device__ __forceinline__ void gemm_pass(uint32_t aB, uint32_t bB, float (&acc)[2][8][4])
{
    #pragma unroll
    for (int k = 0; k < 8; k++) {
        uint32_t a0[4], a1[4];
        ldsm4(a0, aB + k*32);
        ldsm4(a1, aB + 16*LDT*2 + k*32);
        #pragma unroll
        for (int ntp = 0; ntp < 4; ntp++) {
            uint32_t b[4];
            ldsm4(b, bB + ntp*16*LDT*2 + k*32);
            mma16816(acc[0][2*ntp+0], a0, b[0], b[1]);
            mma16816(acc[1][2*ntp+0], a1, b[0], b[1]);
            mma16816(acc[0][2*ntp+1], a0, b[2], b[3]);
            mma16816(acc[1][2*ntp+1], a1, b[2], b[3]);
        }
    }
}

__global__ __launch_bounds__(256, 1)
void k_ffn_mma(const float* __restrict__ b1, const float* __restrict__ b2,
               const float* __restrict__ ln2_g, const float* __restrict__ ln2_b,
               float* __restrict__ d_out)
{
    extern __shared__ __align__(16) char smem[];
    __nv_bfloat16* sAh = reinterpret_cast<__nv_bfloat16*>(smem);
    __nv_bfloat16* sAl = sAh + TILE_E;
    __nv_bfloat16* sHh = sAl + TILE_E;
    __nv_bfloat16* sHl = sHh + TILE_E;

    const uint32_t sb  = (uint32_t)__cvta_generic_to_shared(smem);
    const uint32_t AH = sb, AL = AH + T_BYTES, HHp = AL + T_BYTES,
                   HL = HHp + T_BYTES, BH = HL + T_BYTES, BL = BH + T_BYTES;

    const int tid  = threadIdx.x;
    const int wid  = tid >> 5;
    const int lane = tid & 31;
    const int qr   = lane >> 2;          // 0..7
    const int qc   = (lane & 3) << 1;    // 0,2,4,6
    const int mbase = (wid >> 1) * 32;
    const int nbase = (wid & 1) * 64;
    const int base  = blockIdx.x * 128;

    // per-thread ldmatrix lane offsets (bytes)
    const uint32_t aoff = (uint32_t)(((lane & 15)*LDT + (lane >> 4)*8)*2 + mbase*LDT*2);
    const uint32_t boff = (uint32_t)((((lane & 7) + ((lane >> 4) << 3))*LDT
                                      + ((lane >> 3) & 1)*8)*2 + nbase*LDT*2);

    // ---- issue W1(0) staging via cp.async (hi+lo contiguous 69632B) ----
    {
        const char* src = reinterpret_cast<const char*>(g_wb);
        for (int i = tid; i < 2*T_BYTES/16; i += 256)
            cpa16(BH + i*16, src + i*16);
    }

    // ---- block 0: seg_mask all_seg fix (after k_attn, overlapped) ----
    if (blockIdx.x == 0 && tid < 128) {
        float allm = 1.0f;
        #pragma unroll 4
        for (int s = 0; s < S_; s++)
            allm = fminf(allm, d_out[OUT_ELEMS + tid*S_ + s]);
        if (allm > 0.5f) d_out[OUT_ELEMS + tid*S_] = 0.0f;
    }

    // ---- stage A = emb tile (bf16 hi/lo) ----
    {
        const float4* eb = reinterpret_cast<const float4*>(g_emb + base*128);
        for (int i = tid; i < 4096; i += 256) {
            int r = i >> 5, c4 = (i & 31) << 2;
            float4 v = eb[i];
            int off = r*LDT + c4;
            *reinterpret_cast<uint2*>(sAh + off) = make_uint2(pk2(v.x,v.y), pk2(v.z,v.w));
            *reinterpret_cast<uint2*>(sAl + off) =
                make_uint2(pk2(blo(v.x),blo(v.y)), pk2(blo(v.z),blo(v.w)));
        }
    }
    cpa_wait();
    __syncthreads();

    float acc2[2][8][4];
    #pragma unroll
    for (int mt = 0; mt < 2; mt++)
        #pragma unroll
        for (int nt = 0; nt < 8; nt++)
            #pragma unroll
            for (int c = 0; c < 4; c++) acc2[mt][nt][c] = 0.f;

    for (int kc = 0; kc < 3; kc++) {
        // ---- layer1: acc1 = A @ W1c (3 passes) ----
        float acc1[2][8][4];
        #pragma unroll
        for (int mt = 0; mt < 2; mt++)
            #pragma unroll
            for (int nt = 0; nt < 8; nt++)
                #pragma unroll
                for (int c = 0; c < 4; c++) acc1[mt][nt][c] = 0.f;
        gemm_pass(AH + aoff, BH + boff, acc1);
        gemm_pass(AH + aoff, BL + boff, acc1);
        gemm_pass(AL + aoff, BH + boff, acc1);

        // ---- relu + bias + split -> sH ----
        #pragma unroll
        for (int mt = 0; mt < 2; mt++)
            #pragma unroll
            for (int nt = 0; nt < 8; nt++) {
                const int row = mbase + mt*16 + qr;
                const int col = nbase + nt*8 + qc;
                const int cg  = kc*128 + col;
                float v0 = fmaxf(acc1[mt][nt][0] + __ldg(&b1[cg]),   0.f);
                float v1 = fmaxf(acc1[mt][nt][1] + __ldg(&b1[cg+1]), 0.f);
                float v2 = fmaxf(acc1[mt][nt][2] + __ldg(&b1[cg]),   0.f);
                float v3 = fmaxf(acc1[mt][nt][3] + __ldg(&b1[cg+1]), 0.f);
                *reinterpret_cast<uint32_t*>(sHh + row*LDT + col)     = pk2(v0, v1);
                *reinterpret_cast<uint32_t*>(sHl + row*LDT + col)     = pk2(blo(v0), blo(v1));
                *reinterpret_cast<uint32_t*>(sHh + (row+8)*LDT + col) = pk2(v2, v3);
                *reinterpret_cast<uint32_t*>(sHl + (row+8)*LDT + col) = pk2(blo(v2), blo(v3));
            }
        __syncthreads();   // H visible, B buffer free

        // ---- stage W2(kc) ----
        {
            const char* src = reinterpret_cast<const char*>(g_wb + (3+kc)*2*TILE_E);
            for (int i = tid; i < 2*T_BYTES/16; i += 256)
                cpa16(BH + i*16, src + i*16);
        }
        cpa_wait();
        __syncthreads();

        // ---- layer2 partial: acc2 += Hc @ W2c (3 passes) ----
        gemm_pass(HHp + aoff, BH + boff, acc2);
        gemm_pass(HHp + aoff, BL + boff, acc2);
        gemm_pass(HL  + aoff, BH + boff, acc2);

        if (kc < 2) {
            __syncthreads();   // B free
            const char* src = reinterpret_cast<const char*>(g_wb + (kc+1)*2*TILE_E);
            for (int i = tid; i < 2*T_BYTES/16; i += 256)
                cpa16(BH + i*16, src + i*16);
            cpa_wait();
            __syncthreads();
        }
    }
    __syncthreads();

    // ---- dump acc2 + bias + residual to f32 smem buffer [128][132] ----
    float* sF = reinterpret_cast<float*>(smem);
    #pragma unroll
    for (int mt = 0; mt < 2; mt++)
        #pragma unroll
        for (int nt = 0; nt < 8; nt++) {
            const int row = mbase + mt*16 + qr;
            const int col = nbase + nt*8 + qc;
            const float2 e0 = *reinterpret_cast<const float2*>(&g_emb[(base+row)*128 + col]);
            const float2 e1 = *reinterpret_cast<const float2*>(&g_emb[(base+row+8)*128 + col]);
            const float bb0 = __ldg(&b2[col]), bb1 = __ldg(&b2[col+1]);
            sF[row*132 + col]       = acc2[mt][nt][0] + bb0 + e0.x;
            sF[row*132 + col + 1]   = acc2[mt][nt][1] + bb1 + e0.y;
            sF[(row+8)*132 + col]   = acc2[mt][nt][2] + bb0 + e1.x;
            sF[(row+8)*132 + col+1] = acc2[mt][nt][3] + bb1 + e1.y;
        }
    __syncthreads();

    // ---- LN2 + transposed store ----
    if (tid < 128) {
        const int row = tid;
        float sum = 0.f, sq = 0.f;
        #pragma unroll 8
        for (int c = 0; c < 128; c++) {
            float v = sF[row*132 + c];
            sum += v; sq += v*v;
        }
        const float mu = sum * (1.0f/128.0f);
        const float istd = rsqrtf(sq*(1.0f/128.0f) - mu*mu + 1e-5f);

        const int n = base + row;
        const int s = n % S_;
        const int bm = n / S_;
        float* op = d_out + (((s*B_ + (bm >> 3))*M_ + (bm & 7)) << 7);
        #pragma unroll 4
        for (int c = 0; c < 128; c += 4) {
            float4 o4;
            o4.x = (sF[row*132+c+0]-mu)*istd*__ldg(&ln2_g[c+0]) + __ldg(&ln2_b[c+0]);
            o4.y = (sF[row*132+c+1]-mu)*istd*__ldg(&ln2_g[c+1]) + __ldg(&ln2_b[c+1]);
            o4.z = (sF[row*132+c+2]-mu)*istd*__ldg(&ln2_g[c+2]) + __ldg(&ln2_b[c+2]);
            o4.w = (sF[row*132+c+3]-mu)*istd*__ldg(&ln2_g[c+3]) + __ldg(&ln2_b[c+3]);
            *reinterpret_cast<float4*>(op + c) = o4;
        }
    }
}

// ================= launcher =================
extern "C" void kernel_launch(void* const* d_in, const int* in_sizes, int n_in,
                              void* d_out, int out_size)
{
    const float* roads  = (const float*)d_in[0];
    const float* ms     = (const float*)d_in[2];
    const float* lin_w  = (const float*)d_in[3];
    const float* lin_b  = (const float*)d_in[4];
    const float* wq     = (const float*)d_in[5];
    const float* wk     = (const float*)d_in[6];
    const float* wv     = (const float*)d_in[7];
    const float* bq     = (const float*)d_in[8];
    const float* bk     = (const float*)d_in[9];
    const float* bv     = (const float*)d_in[10];
    const float* out_w  = (const float*)d_in[11];
    const float* out_b  = (const float*)d_in[12];
    const float* ln1_g  = (const float*)d_in[13];
    const float* ln1_b  = (const float*)d_in[14];
    const float* w1     = (const float*)d_in[15];
    const float* b1     = (const float*)d_in[16];
    const float* w2     = (const float*)d_in[17];
    const float* b2     = (const float*)d_in[18];
    const float* ln2_g  = (const float*)d_in[19];
    const float* ln2_b  = (const float*)d_in[20];
    float* out = (float*)d_out;

    cudaFuncSetAttribute(k_pre7, cudaFuncAttributeMaxDynamicSharedMemorySize, PRE_DSMEM);
    cudaFuncSetAttribute(k_ffn_mma, cudaFuncAttributeMaxDynamicSharedMemorySize, K3_DSMEM);

    k_pre7<<<7, 256, PRE_DSMEM>>>(ms, lin_w, lin_b, wq, wk, wv, bq, bk, bv, out_w, out_b, w1, w2);
    k_attn<<<N_SEG/8, 256>>>(roads, ln1_g, ln1_b, out);
    k_ffn_mma<<<N_SEG/128, 256, K3_DSMEM>>>(b1, b2, ln2_g, ln2_b, out);
}